// round 14
// baseline (speedup 1.0000x reference)
#include <cuda_runtime.h>

// Truncated path signature, D=6, depth K=4, L=65536 points (65535 increments).
// Output: [S1(6), S2(36), S3(216), S4(1296)] = 1554 floats.
//
// Single persistent kernel, 148 blocks x 576 threads (1 block/SM by regs;
// GB300 has 152 SMs so all blocks co-resident -> software grid barrier safe).
//   Phase 1: 16 chunks x 28 steps per block (36 threads/chunk, thread owns
//            prefix ab), then ELEMENT-PARALLEL 16->1 tree fold (R13's
//            36-thread-per-merge folds were the bottleneck: ~12 serial levels
//            x ~1.2us; element-parallel levels cost ~0.15us each).
//   Phase 2: blocks 0..9 element-parallel fold 16 sigs each: 148 -> 10.
//   Phase 3: block 0 folds 10 -> 1 (zero-padded to 16; zero sig = Chen
//            identity), writes d_out.
// Grid barriers: generation-counting atomic (monotone across graph replays).

#define DD 6
#define NINC 65535
#define CPB 16
#define SPC 28                       // 148*16*28 = 66304 >= 65535, zero-padded
#define BLOCKS_A 148
#define THREADS_A (CPB * 36)         // 576
#define SIG 1554
#define O2 6
#define O3 42
#define O4 258
#define G1 16
#define B1CNT ((BLOCKS_A + G1 - 1) / G1)   // 10

__device__ float g_sigA[BLOCKS_A * SIG];
__device__ float g_sigB[B1CNT * SIG];
__device__ unsigned int g_bar;       // zero-init; monotone across replays

__device__ __forceinline__ void grid_barrier()
{
    __syncthreads();
    if (threadIdx.x == 0) {
        __threadfence();                                   // release prior writes
        unsigned int ticket = atomicAdd(&g_bar, 1u);
        unsigned int target = (ticket / BLOCKS_A + 1u) * BLOCKS_A;
        unsigned int v;
        do {
            asm volatile("ld.acquire.gpu.u32 %0, [%1];" : "=r"(v) : "l"(&g_bar));
        } while (v < target);
    }
    __syncthreads();
}

// ---------------------------------------------------------------------------
// Element-parallel Chen product: one output element of C = A (x) B.
//   C_k = A_k + B_k + sum_{i=1}^{k-1} A_i (x) B_{k-i}   (A = left/earlier)
// Zero signature acts as identity (all cross terms vanish), enabling
// power-of-2 padding.
// ---------------------------------------------------------------------------
__device__ __forceinline__ float chen_elem(
    const float* __restrict__ A, const float* __restrict__ B, int e)
{
    float r = A[e] + B[e];
    if (e >= O4) {                    // level 4: m = a*216 + b*36 + c*6 + d
        int m = e - O4;
        r = fmaf(A[m / 216],     B[O3 + m % 216], r);   // A1 (x) B3
        r = fmaf(A[O2 + m / 36], B[O2 + m % 36],  r);   // A2 (x) B2
        r = fmaf(A[O3 + m / 6],  B[m % 6],        r);   // A3 (x) B1
    } else if (e >= O3) {             // level 3: m = a*36 + b*6 + c
        int m = e - O3;
        r = fmaf(A[m / 36],      B[O2 + m % 36],  r);   // A1 (x) B2
        r = fmaf(A[O2 + m / 6],  B[m % 6],        r);   // A2 (x) B1
    } else if (e >= O2) {             // level 2: m = a*6 + b
        int m = e - O2;
        r = fmaf(A[m / 6],       B[m % 6],        r);   // A1 (x) B1
    }
    return r;
}

// One tree level: THREADS_A/TPM merges, each with TPM threads; merge g folds
// slot g*2*stride (left) with slot g*2*stride + stride (right), in place.
template<int TPM>
__device__ __forceinline__ void chen_level(float* sh, int stride, int tid)
{
    const int g  = tid / TPM;
    const int lr = tid - g * TPM;
    float* A = sh + (g * 2 * stride) * SIG;
    const float* B = A + stride * SIG;

    constexpr int EPT = (SIG + TPM - 1) / TPM;
    float val[EPT];
#pragma unroll
    for (int i = 0; i < EPT; i++) {
        int e = lr + i * TPM;
        if (e < SIG) val[i] = chen_elem(A, B, e);
    }
    __syncthreads();
#pragma unroll
    for (int i = 0; i < EPT; i++) {
        int e = lr + i * TPM;
        if (e < SIG) A[e] = val[i];
    }
    __syncthreads();
}

// Fold 16 signatures (slots 0..15 in shared) into slot 0.
__device__ __forceinline__ void fold16(float* sh, int tid)
{
    chen_level<72> (sh, 1, tid);   // 8 merges
    chen_level<144>(sh, 2, tid);   // 4 merges
    chen_level<288>(sh, 4, tid);   // 2 merges
    chen_level<576>(sh, 8, tid);   // 1 merge
}

// ---------------------------------------------------------------------------
__global__ __launch_bounds__(THREADS_A, 1) void sig_kernel(
    const float* __restrict__ x, float* __restrict__ out)
{
    // Dynamic smem reused: increments (CPB*SPC*8 = 3584 floats), then
    // 16 sigs (16*1554 = 24864 floats = 99456 B).
    extern __shared__ __align__(16) float sh[];

    const int tid = threadIdx.x;
    const int g36 = tid / 36;             // chunk 0..15
    const int ab  = tid - g36 * 36;
    const int a   = ab / 6;
    const int b   = ab - a * 6;

    // ---- Phase 1: chunk signatures + in-block fold ----------------------
    {
        const long blkIncBase = (long)blockIdx.x * (CPB * SPC);
        for (int idx = tid; idx < CPB * SPC * DD; idx += THREADS_A) {
            int s = idx / DD;
            int j = idx - s * DD;
            long gidx = blkIncBase + s;
            float v = 0.0f;
            if (gidx < (long)NINC)
                v = x[(gidx + 1) * DD + j] - x[gidx * DD + j];
            sh[s * 8 + j] = v;
        }
        __syncthreads();

        float s1 = 0.0f, s2 = 0.0f;
        float s3[6], s4[36];
#pragma unroll
        for (int c = 0; c < 6; c++) s3[c] = 0.0f;
#pragma unroll
        for (int k = 0; k < 36; k++) s4[k] = 0.0f;

        const float* base = &sh[g36 * SPC * 8];
        const float THIRD = 1.0f / 3.0f;

#pragma unroll 1
        for (int t = 0; t < SPC; t++) {
            const float* p = base + t * 8;
            const float4* q = (const float4*)p;
            float4 f0 = q[0], f1 = q[1];
            float vv[6] = { f0.x, f0.y, f0.z, f0.w, f1.x, f1.y };

            float vA = p[a], vB = p[b];
            float tA = vA * THIRD, tB = vB * THIRD;

            // Horner chains (all reads of s1,s2,s3 are pre-update values)
            float V1 = fmaf(vA, 0.25f, s1);
            float V2 = fmaf(V1, tB, s2);
            float W1 = s1 + tA;
            float W2 = fmaf(W1, 0.5f * vB, s2);
            float U1 = fmaf(vA, 0.5f, s1);
            s2 = fmaf(U1, vB, s2);
            s1 += vA;
            float V2h = 0.5f * V2;

#pragma unroll
            for (int c = 0; c < 6; c++) {
                float V3 = fmaf(V2h, vv[c], s3[c]);    // uses old s3
                s3[c]    = fmaf(W2,  vv[c], s3[c]);
#pragma unroll
                for (int d = 0; d < 6; d++)
                    s4[c * 6 + d] = fmaf(V3, vv[d], s4[c * 6 + d]);
            }
        }

        __syncthreads();      // increments dead; reuse buffer for sigs
        {
            float* o = sh + g36 * SIG;
            if (b == 0) o[a] = s1;
            o[O2 + ab] = s2;
#pragma unroll
            for (int c = 0; c < 6; c++) o[O3 + ab * 6 + c] = s3[c];
#pragma unroll
            for (int k = 0; k < 36; k++) o[O4 + ab * 36 + k] = s4[k];
        }
        __syncthreads();

        fold16(sh, tid);

        for (int k = tid; k < SIG; k += THREADS_A)
            g_sigA[(long)blockIdx.x * SIG + k] = sh[k];
    }

    grid_barrier();

    // ---- Phase 2: 148 -> 10 ---------------------------------------------
    if (blockIdx.x < B1CNT) {
        const int base = blockIdx.x * G1;
        int cnt = BLOCKS_A - base;
        if (cnt > G1) cnt = G1;

        for (int k = tid; k < cnt * SIG; k += THREADS_A)
            sh[k] = g_sigA[(long)base * SIG + k];
        for (int k = cnt * SIG + tid; k < G1 * SIG; k += THREADS_A)
            sh[k] = 0.0f;                       // identity padding
        __syncthreads();

        fold16(sh, tid);

        for (int k = tid; k < SIG; k += THREADS_A)
            g_sigB[(long)blockIdx.x * SIG + k] = sh[k];
    }

    grid_barrier();

    // ---- Phase 3: 10 -> 1 -------------------------------------------------
    if (blockIdx.x == 0) {
        for (int k = tid; k < B1CNT * SIG; k += THREADS_A)
            sh[k] = g_sigB[k];
        for (int k = B1CNT * SIG + tid; k < G1 * SIG; k += THREADS_A)
            sh[k] = 0.0f;                       // identity padding
        __syncthreads();

        fold16(sh, tid);

        for (int k = tid; k < SIG; k += THREADS_A)
            out[k] = sh[k];
    }
}

// ---------------------------------------------------------------------------
extern "C" void kernel_launch(void* const* d_in, const int* in_sizes, int n_in,
                              void* d_out, int out_size)
{
    const float* x = (const float*)d_in[0];
    float* out = (float*)d_out;
    (void)in_sizes; (void)n_in; (void)out_size;

    const int smem = G1 * SIG * (int)sizeof(float);   // 99456 B
    cudaFuncSetAttribute(sig_kernel,
                         cudaFuncAttributeMaxDynamicSharedMemorySize, smem);

    sig_kernel<<<BLOCKS_A, THREADS_A, smem>>>(x, out);
}

// round 15
// speedup vs baseline: 1.1884x; 1.1884x over previous
#include <cuda_runtime.h>

// Truncated path signature, D=6, depth K=4, L=65536 points (65535 increments).
// Output: [S1(6), S2(36), S3(216), S4(1296)] = 1554 floats.
//
// Single kernel, 148 blocks x 576 threads.
//   Phase 1: 16 chunks x 28 steps per block (36 threads/chunk, thread owns
//            prefix ab), then ping-pong element-parallel 16->1 fold (no
//            register buffering -- R14's val[] arrays forced regs 96->72 and
//            spilled the phase-1 s4 accumulators), write g_sigA[blk].
//   Phase 2: LAST block to finish in each group of 16 (monotone atomic
//            counter, exact-once per graph replay via modulo) folds its
//            group: 148 -> 10 (g_sigB).
//   Phase 3: last group-folder folds 10 -> 1 (zero-pad to 16; zero sig is the
//            Chen identity) and writes d_out.  No grid-wide spin barriers.

#define DD 6
#define NINC 65535
#define CPB 16
#define SPC 28                       // 148*16*28 = 66304 >= 65535, zero-padded
#define BLOCKS_A 148
#define THREADS_A (CPB * 36)         // 576
#define SIG 1554
#define O2 6
#define O3 42
#define O4 258
#define G1 16
#define B1CNT ((BLOCKS_A + G1 - 1) / G1)   // 10
#define SLOTS 24                     // bufA: 16 sigs, bufB: 8 sigs

__device__ float g_sigA[BLOCKS_A * SIG];
__device__ float g_sigB[B1CNT * SIG];
__device__ unsigned int g_cnt[B1CNT];   // zero-init; monotone across replays
__device__ unsigned int g_fin;          // zero-init; monotone across replays

// ---------------------------------------------------------------------------
// Element-parallel Chen product: one output element of C = A (x) B.
//   C_k = A_k + B_k + sum_{i=1}^{k-1} A_i (x) B_{k-i}   (A = left/earlier)
// Zero signature acts as identity, enabling power-of-2 padding.
// ---------------------------------------------------------------------------
__device__ __forceinline__ float chen_elem(
    const float* __restrict__ A, const float* __restrict__ B, int e)
{
    float r = A[e] + B[e];
    if (e >= O4) {                    // level 4: m = a*216 + b*36 + c*6 + d
        int m = e - O4;
        r = fmaf(A[m / 216],     B[O3 + m % 216], r);   // A1 (x) B3
        r = fmaf(A[O2 + m / 36], B[O2 + m % 36],  r);   // A2 (x) B2
        r = fmaf(A[O3 + m / 6],  B[m % 6],        r);   // A3 (x) B1
    } else if (e >= O3) {             // level 3: m = a*36 + b*6 + c
        int m = e - O3;
        r = fmaf(A[m / 36],      B[O2 + m % 36],  r);   // A1 (x) B2
        r = fmaf(A[O2 + m / 6],  B[m % 6],        r);   // A2 (x) B1
    } else if (e >= O2) {             // level 2: m = a*6 + b
        int m = e - O2;
        r = fmaf(A[m / 6],       B[m % 6],        r);   // A1 (x) B1
    }
    return r;
}

// One ping-pong level: 576/TPM merges; merge g reads src slots 2g,2g+1 and
// writes dst slot g. No aliasing -> no register staging, one barrier.
template<int TPM>
__device__ __forceinline__ void chen_level_pp(
    const float* __restrict__ src, float* __restrict__ dst, int tid)
{
    const int g  = tid / TPM;
    const int lr = tid - g * TPM;
    const float* A = src + (2 * g) * SIG;
    const float* B = A + SIG;
    float* C = dst + g * SIG;
    for (int e = lr; e < SIG; e += TPM)
        C[e] = chen_elem(A, B, e);
    __syncthreads();
}

// Fold 16 signatures in bufA into bufA slot 0 (bufB = scratch, 8 slots).
__device__ __forceinline__ void fold16(float* bufA, float* bufB, int tid)
{
    chen_level_pp<72> (bufA, bufB, tid);   // 16 -> 8
    chen_level_pp<144>(bufB, bufA, tid);   //  8 -> 4
    chen_level_pp<288>(bufA, bufB, tid);   //  4 -> 2
    chen_level_pp<576>(bufB, bufA, tid);   //  2 -> 1  (result: bufA[0..SIG))
}

// ---------------------------------------------------------------------------
__global__ __launch_bounds__(THREADS_A, 1) void sig_kernel(
    const float* __restrict__ x, float* __restrict__ out)
{
    // Dynamic smem: bufA = 16 sigs (increments overlay it first), bufB = 8.
    extern __shared__ __align__(16) float sh[];
    float* bufA = sh;
    float* bufB = sh + G1 * SIG;
    __shared__ unsigned int s_role, s_fin;

    const int tid = threadIdx.x;
    const int g36 = tid / 36;             // chunk 0..15
    const int ab  = tid - g36 * 36;
    const int a   = ab / 6;
    const int b   = ab - a * 6;

    // ---- Phase 1: chunk signatures + in-block fold ----------------------
    {
        const long blkIncBase = (long)blockIdx.x * (CPB * SPC);
        for (int idx = tid; idx < CPB * SPC * DD; idx += THREADS_A) {
            int s = idx / DD;
            int j = idx - s * DD;
            long gidx = blkIncBase + s;
            float v = 0.0f;
            if (gidx < (long)NINC)
                v = x[(gidx + 1) * DD + j] - x[gidx * DD + j];
            bufA[s * 8 + j] = v;
        }
        __syncthreads();

        float s1 = 0.0f, s2 = 0.0f;
        float s3[6], s4[36];
#pragma unroll
        for (int c = 0; c < 6; c++) s3[c] = 0.0f;
#pragma unroll
        for (int k = 0; k < 36; k++) s4[k] = 0.0f;

        const float* base = &bufA[g36 * SPC * 8];
        const float THIRD = 1.0f / 3.0f;

#pragma unroll 1
        for (int t = 0; t < SPC; t++) {
            const float* p = base + t * 8;
            const float4* q = (const float4*)p;
            float4 f0 = q[0], f1 = q[1];
            float vv[6] = { f0.x, f0.y, f0.z, f0.w, f1.x, f1.y };

            float vA = p[a], vB = p[b];
            float tA = vA * THIRD, tB = vB * THIRD;

            // Horner chains (all reads of s1,s2,s3 are pre-update values)
            float V1 = fmaf(vA, 0.25f, s1);
            float V2 = fmaf(V1, tB, s2);
            float W1 = s1 + tA;
            float W2 = fmaf(W1, 0.5f * vB, s2);
            float U1 = fmaf(vA, 0.5f, s1);
            s2 = fmaf(U1, vB, s2);
            s1 += vA;
            float V2h = 0.5f * V2;

#pragma unroll
            for (int c = 0; c < 6; c++) {
                float V3 = fmaf(V2h, vv[c], s3[c]);    // uses old s3
                s3[c]    = fmaf(W2,  vv[c], s3[c]);
#pragma unroll
                for (int d = 0; d < 6; d++)
                    s4[c * 6 + d] = fmaf(V3, vv[d], s4[c * 6 + d]);
            }
        }

        __syncthreads();      // increments dead; bufA becomes 16 sig slots
        {
            float* o = bufA + g36 * SIG;
            if (b == 0) o[a] = s1;
            o[O2 + ab] = s2;
#pragma unroll
            for (int c = 0; c < 6; c++) o[O3 + ab * 6 + c] = s3[c];
#pragma unroll
            for (int k = 0; k < 36; k++) o[O4 + ab * 36 + k] = s4[k];
        }
        __syncthreads();

        fold16(bufA, bufB, tid);

        for (int k = tid; k < SIG; k += THREADS_A)
            g_sigA[(long)blockIdx.x * SIG + k] = bufA[k];
    }

    // ---- Phase 2: last block of each group folds 16 -> 1 -----------------
    const int grp = blockIdx.x / G1;
    const int gbase = grp * G1;
    const int gsize = (BLOCKS_A - gbase < G1) ? (BLOCKS_A - gbase) : G1;

    __syncthreads();
    if (tid == 0) {
        __threadfence();                                  // release g_sigA
        unsigned int old = atomicAdd(&g_cnt[grp], 1u);
        s_role = (((old + 1u) % (unsigned)gsize) == 0u) ? 1u : 0u;
    }
    __syncthreads();
    if (!s_role) return;

    __threadfence();                                      // acquire
    for (int k = tid; k < gsize * SIG; k += THREADS_A)
        bufA[k] = __ldcg(&g_sigA[(long)gbase * SIG + k]);
    for (int k = gsize * SIG + tid; k < G1 * SIG; k += THREADS_A)
        bufA[k] = 0.0f;                                   // identity padding
    __syncthreads();

    fold16(bufA, bufB, tid);

    for (int k = tid; k < SIG; k += THREADS_A)
        g_sigB[(long)grp * SIG + k] = bufA[k];

    // ---- Phase 3: last group-folder folds 10 -> 1 -------------------------
    __syncthreads();
    if (tid == 0) {
        __threadfence();                                  // release g_sigB
        unsigned int old = atomicAdd(&g_fin, 1u);
        s_fin = (((old + 1u) % (unsigned)B1CNT) == 0u) ? 1u : 0u;
    }
    __syncthreads();
    if (!s_fin) return;

    __threadfence();                                      // acquire
    for (int k = tid; k < B1CNT * SIG; k += THREADS_A)
        bufA[k] = __ldcg(&g_sigB[k]);
    for (int k = B1CNT * SIG + tid; k < G1 * SIG; k += THREADS_A)
        bufA[k] = 0.0f;                                   // identity padding
    __syncthreads();

    fold16(bufA, bufB, tid);

    for (int k = tid; k < SIG; k += THREADS_A)
        out[k] = bufA[k];
}

// ---------------------------------------------------------------------------
extern "C" void kernel_launch(void* const* d_in, const int* in_sizes, int n_in,
                              void* d_out, int out_size)
{
    const float* x = (const float*)d_in[0];
    float* out = (float*)d_out;
    (void)in_sizes; (void)n_in; (void)out_size;

    const int smem = SLOTS * SIG * (int)sizeof(float);   // 149184 B
    cudaFuncSetAttribute(sig_kernel,
                         cudaFuncAttributeMaxDynamicSharedMemorySize, smem);

    sig_kernel<<<BLOCKS_A, THREADS_A, smem>>>(x, out);
}

// round 16
// speedup vs baseline: 1.3299x; 1.1191x over previous
#include <cuda_runtime.h>

// Truncated path signature, D=6, depth K=4, L=65536 points (65535 increments).
// Output: [S1(6), S2(36), S3(216), S4(1296)] = 1554 floats.
//
// THREE kernels, split along the register-allocation boundary (R14/R15 showed
// element-parallel merge code fused into the stage-A kernel drags ptxas's
// global reg target from 96 to ~69 and spills the hot-loop s4 accumulators):
//   stageA: 148 blocks x 576 threads; 16 chunks x 28 steps (36 threads/chunk,
//           thread owns prefix ab), then 36-thread ChenRegs in-block tree fold
//           (this exact pairing holds 96 regs) -> g_sigA[148].
//   merge1: 10 blocks x 576 threads; element-parallel ping-pong fold of 16
//           sigs each (zero-pad; zero sig = Chen identity): 148 -> 10.
//   merge2: 1 block; fold 10 -> 1, write d_out.

#define DD 6
#define NINC 65535
#define CPB 16
#define SPC 28                       // 148*16*28 = 66304 >= 65535, zero-padded
#define BLOCKS_A 148
#define THREADS_A (CPB * 36)         // 576
#define SIG 1554
#define O2 6
#define O3 42
#define O4 258
#define G1 16
#define B1CNT ((BLOCKS_A + G1 - 1) / G1)   // 10
#define MSLOTS 24                    // merge smem: bufA 16 sigs + bufB 8 sigs

__device__ float g_sigA[BLOCKS_A * SIG];
__device__ float g_sigB[B1CNT * SIG];

// ===========================================================================
// 36-thread ownership Chen fold (used ONLY inside stageA; holds 96 regs there)
//   C_k = A_k + B_k + sum_{i=1}^{k-1} A_i (x) B_{k-i}   (A = left/earlier)
// ===========================================================================
struct ChenRegs { float c1, c2, c3[6], c4[36]; };

__device__ __forceinline__ void chen_compute(
    const float* __restrict__ A, const float* __restrict__ B,
    int t, int a, int b, ChenRegs& r)
{
    float A1a  = A[a];
    float A2ab = A[O2 + t];
    float A3l[6], B1l[6];
#pragma unroll
    for (int c = 0; c < 6; c++) A3l[c] = A[O3 + t * 6 + c];
#pragma unroll
    for (int d = 0; d < 6; d++) B1l[d] = B[d];

    r.c1 = A1a + B[a];
    r.c2 = fmaf(A1a, B1l[b], A2ab + B[O2 + t]);

#pragma unroll
    for (int c = 0; c < 6; c++) {
        float v = A3l[c] + B[O3 + t * 6 + c];
        v = fmaf(A1a,  B[O2 + b * 6 + c], v);   // A1 (x) B2
        v = fmaf(A2ab, B1l[c],            v);   // A2 (x) B1
        r.c3[c] = v;
    }
#pragma unroll
    for (int k = 0; k < 36; k++) {              // k = c*6 + d
        float v = A[O4 + t * 36 + k] + B[O4 + t * 36 + k];
        v = fmaf(A2ab,        B[O2 + k],          v);   // A2 (x) B2
        v = fmaf(A1a,         B[O3 + b * 36 + k], v);   // A1 (x) B3
        v = fmaf(A3l[k / 6],  B1l[k % 6],         v);   // A3 (x) B1
        r.c4[k] = v;
    }
}

__device__ __forceinline__ void chen_write(
    float* __restrict__ A, int t, int a, int b, const ChenRegs& r)
{
    if (b == 0) A[a] = r.c1;
    A[O2 + t] = r.c2;
#pragma unroll
    for (int c = 0; c < 6; c++) A[O3 + t * 6 + c] = r.c3[c];
#pragma unroll
    for (int k = 0; k < 36; k++) A[O4 + t * 36 + k] = r.c4[k];
}

// Order-preserving in-place tree fold over 16 sig slots in shared memory.
__device__ __forceinline__ void tree_fold16(float* sh, int g, int t, int a, int b)
{
#pragma unroll
    for (int s = 1; s < CPB; s *= 2) {
        int i = g * 2 * s;
        bool act = (i + s) < CPB;
        ChenRegs r;
        if (act) chen_compute(sh + i * SIG, sh + (i + s) * SIG, t, a, b, r);
        __syncthreads();
        if (act) chen_write(sh + i * SIG, t, a, b, r);
        __syncthreads();
    }
}

// ===========================================================================
// Stage A
// ===========================================================================
__global__ __launch_bounds__(THREADS_A, 1) void stageA_kernel(const float* __restrict__ x)
{
    // Dynamic smem reused: increments (CPB*SPC*8 = 3584 floats), then
    // 16 chunk sigs (24864 floats = 99456 B).
    extern __shared__ __align__(16) float sh[];

    const int tid = threadIdx.x;
    const int g36 = tid / 36;             // chunk 0..15
    const int ab  = tid - g36 * 36;
    const int a   = ab / 6;
    const int b   = ab - a * 6;

    const long blkIncBase = (long)blockIdx.x * (CPB * SPC);
    for (int idx = tid; idx < CPB * SPC * DD; idx += THREADS_A) {
        int s = idx / DD;
        int j = idx - s * DD;
        long gidx = blkIncBase + s;
        float v = 0.0f;
        if (gidx < (long)NINC)
            v = x[(gidx + 1) * DD + j] - x[gidx * DD + j];
        sh[s * 8 + j] = v;
    }
    __syncthreads();

    float s1 = 0.0f, s2 = 0.0f;
    float s3[6], s4[36];
#pragma unroll
    for (int c = 0; c < 6; c++) s3[c] = 0.0f;
#pragma unroll
    for (int k = 0; k < 36; k++) s4[k] = 0.0f;

    const float* base = &sh[g36 * SPC * 8];
    const float THIRD = 1.0f / 3.0f;

#pragma unroll 1
    for (int t = 0; t < SPC; t++) {
        const float* p = base + t * 8;
        const float4* q = (const float4*)p;
        float4 f0 = q[0], f1 = q[1];
        float vv[6] = { f0.x, f0.y, f0.z, f0.w, f1.x, f1.y };

        float vA = p[a], vB = p[b];
        float tA = vA * THIRD, tB = vB * THIRD;

        // Horner chains (all reads of s1,s2,s3 are pre-update values)
        float V1 = fmaf(vA, 0.25f, s1);
        float V2 = fmaf(V1, tB, s2);
        float W1 = s1 + tA;
        float W2 = fmaf(W1, 0.5f * vB, s2);
        float U1 = fmaf(vA, 0.5f, s1);
        s2 = fmaf(U1, vB, s2);
        s1 += vA;
        float V2h = 0.5f * V2;

#pragma unroll
        for (int c = 0; c < 6; c++) {
            float V3 = fmaf(V2h, vv[c], s3[c]);    // uses old s3
            s3[c]    = fmaf(W2,  vv[c], s3[c]);
#pragma unroll
            for (int d = 0; d < 6; d++)
                s4[c * 6 + d] = fmaf(V3, vv[d], s4[c * 6 + d]);
        }
    }

    __syncthreads();      // increments dead; buffer becomes 16 sig slots
    {
        float* o = sh + g36 * SIG;
        if (b == 0) o[a] = s1;
        o[O2 + ab] = s2;
#pragma unroll
        for (int c = 0; c < 6; c++) o[O3 + ab * 6 + c] = s3[c];
#pragma unroll
        for (int k = 0; k < 36; k++) o[O4 + ab * 36 + k] = s4[k];
    }
    __syncthreads();

    tree_fold16(sh, g36, ab, a, b);

    for (int k = tid; k < SIG; k += THREADS_A)
        g_sigA[(long)blockIdx.x * SIG + k] = sh[k];
}

// ===========================================================================
// Element-parallel Chen merge (separate kernels; reg pressure harmless here)
// ===========================================================================
__device__ __forceinline__ float chen_elem(
    const float* __restrict__ A, const float* __restrict__ B, int e)
{
    float r = A[e] + B[e];
    if (e >= O4) {                    // level 4: m = a*216 + b*36 + c*6 + d
        int m = e - O4;
        r = fmaf(A[m / 216],     B[O3 + m % 216], r);   // A1 (x) B3
        r = fmaf(A[O2 + m / 36], B[O2 + m % 36],  r);   // A2 (x) B2
        r = fmaf(A[O3 + m / 6],  B[m % 6],        r);   // A3 (x) B1
    } else if (e >= O3) {             // level 3: m = a*36 + b*6 + c
        int m = e - O3;
        r = fmaf(A[m / 36],      B[O2 + m % 36],  r);   // A1 (x) B2
        r = fmaf(A[O2 + m / 6],  B[m % 6],        r);   // A2 (x) B1
    } else if (e >= O2) {             // level 2: m = a*6 + b
        int m = e - O2;
        r = fmaf(A[m / 6],       B[m % 6],        r);   // A1 (x) B1
    }
    return r;
}

// One ping-pong level: 576/TPM merges; merge g reads src slots 2g,2g+1,
// writes dst slot g. No aliasing -> single barrier, no staging.
template<int TPM>
__device__ __forceinline__ void chen_level_pp(
    const float* __restrict__ src, float* __restrict__ dst, int tid)
{
    const int g  = tid / TPM;
    const int lr = tid - g * TPM;
    const float* A = src + (2 * g) * SIG;
    const float* B = A + SIG;
    float* C = dst + g * SIG;
    for (int e = lr; e < SIG; e += TPM)
        C[e] = chen_elem(A, B, e);
    __syncthreads();
}

__device__ __forceinline__ void fold16_pp(float* bufA, float* bufB, int tid)
{
    chen_level_pp<72> (bufA, bufB, tid);   // 16 -> 8
    chen_level_pp<144>(bufB, bufA, tid);   //  8 -> 4
    chen_level_pp<288>(bufA, bufB, tid);   //  4 -> 2
    chen_level_pp<576>(bufB, bufA, tid);   //  2 -> 1  (result in bufA[0..SIG))
}

__global__ __launch_bounds__(THREADS_A) void merge1_kernel()   // 148 -> 10
{
    extern __shared__ __align__(16) float shm[];
    float* bufA = shm;
    float* bufB = shm + G1 * SIG;
    const int tid = threadIdx.x;
    const int base = blockIdx.x * G1;
    int cnt = BLOCKS_A - base;
    if (cnt > G1) cnt = G1;

    for (int k = tid; k < cnt * SIG; k += THREADS_A)
        bufA[k] = g_sigA[(long)base * SIG + k];
    for (int k = cnt * SIG + tid; k < G1 * SIG; k += THREADS_A)
        bufA[k] = 0.0f;                       // identity padding
    __syncthreads();

    fold16_pp(bufA, bufB, tid);

    for (int k = tid; k < SIG; k += THREADS_A)
        g_sigB[(long)blockIdx.x * SIG + k] = bufA[k];
}

__global__ __launch_bounds__(THREADS_A) void merge2_kernel(float* __restrict__ out)  // 10 -> 1
{
    extern __shared__ __align__(16) float shm[];
    float* bufA = shm;
    float* bufB = shm + G1 * SIG;
    const int tid = threadIdx.x;

    for (int k = tid; k < B1CNT * SIG; k += THREADS_A)
        bufA[k] = g_sigB[k];
    for (int k = B1CNT * SIG + tid; k < G1 * SIG; k += THREADS_A)
        bufA[k] = 0.0f;                       // identity padding
    __syncthreads();

    fold16_pp(bufA, bufB, tid);

    for (int k = tid; k < SIG; k += THREADS_A)
        out[k] = bufA[k];
}

// ---------------------------------------------------------------------------
extern "C" void kernel_launch(void* const* d_in, const int* in_sizes, int n_in,
                              void* d_out, int out_size)
{
    const float* x = (const float*)d_in[0];
    float* out = (float*)d_out;
    (void)in_sizes; (void)n_in; (void)out_size;

    const int smemA = G1 * SIG * (int)sizeof(float);      // 99456 B
    const int smemM = MSLOTS * SIG * (int)sizeof(float);  // 149184 B
    static int attr_done = 0;
    if (!attr_done) {
        cudaFuncSetAttribute(stageA_kernel,
                             cudaFuncAttributeMaxDynamicSharedMemorySize, smemA);
        cudaFuncSetAttribute(merge1_kernel,
                             cudaFuncAttributeMaxDynamicSharedMemorySize, smemM);
        cudaFuncSetAttribute(merge2_kernel,
                             cudaFuncAttributeMaxDynamicSharedMemorySize, smemM);
        attr_done = 1;
    }

    stageA_kernel<<<BLOCKS_A, THREADS_A, smemA>>>(x);
    merge1_kernel<<<B1CNT, THREADS_A, smemM>>>();
    merge2_kernel<<<1, THREADS_A, smemM>>>(out);
}